// round 1
// baseline (speedup 1.0000x reference)
#include <cuda_runtime.h>
#include <cuda_bf16.h>

// Problem constants
#define Bv   4
#define Tv   2048
#define Dv   1024
#define NH   16
#define HDim 64
#define BT   (Bv * Tv)          // 8192
#define QKVN (3 * Dv)           // 3072

// ---------------------------------------------------------------------------
// Scratch (device globals; no allocation allowed)
// ---------------------------------------------------------------------------
__device__ float g_qkv[BT * QKVN];   // (B,T,3,H,HD) = 96 MB
__device__ float g_attn[BT * Dv];    // attention output, (B,T,H,HD) = 32 MB

// ---------------------------------------------------------------------------
// Tiled fp32 GEMM: C[M,N] = A[M,K] @ B[K,N], all row-major.
// 128x128 block tile, 8x8 per-thread microtile, BK=8, 256 threads.
// M,N divisible by 128; K divisible by 8 (true for all our shapes).
// ---------------------------------------------------------------------------
#define GBM 128
#define GBN 128
#define GBK 8
#define GTM 8
#define GTN 8

__global__ __launch_bounds__(256, 2)
void sgemm128(const float* __restrict__ A, const float* __restrict__ B,
              float* __restrict__ C, int M, int N, int K)
{
    __shared__ float As[GBK][GBM];
    __shared__ float Bs[GBK][GBN];

    const int tid  = threadIdx.x;
    const int cRow = blockIdx.y;
    const int cCol = blockIdx.x;

    A += (long)cRow * GBM * K;
    B += cCol * GBN;
    C += (long)cRow * GBM * N + cCol * GBN;

    const int aRow = tid >> 1;          // 0..127
    const int aCol = (tid & 1) * 4;     // 0 or 4
    const int bRow = tid >> 5;          // 0..7
    const int bCol = (tid & 31) * 4;    // 0..124

    const int tRow = (tid >> 4) * GTM;  // 0..120
    const int tCol = (tid & 15) * GTN;  // 0..120

    float acc[GTM][GTN] = {};
    float regM[GTM], regN[GTN];

    for (int k0 = 0; k0 < K; k0 += GBK) {
        float4 av = *(const float4*)(A + (long)aRow * K + aCol);
        As[aCol + 0][aRow] = av.x;
        As[aCol + 1][aRow] = av.y;
        As[aCol + 2][aRow] = av.z;
        As[aCol + 3][aRow] = av.w;
        *(float4*)(&Bs[bRow][bCol]) = *(const float4*)(B + (long)bRow * N + bCol);
        __syncthreads();

        A += GBK;
        B += (long)GBK * N;

        #pragma unroll
        for (int k = 0; k < GBK; ++k) {
            #pragma unroll
            for (int i = 0; i < GTM; i += 4) {
                float4 v = *(const float4*)(&As[k][tRow + i]);
                regM[i] = v.x; regM[i+1] = v.y; regM[i+2] = v.z; regM[i+3] = v.w;
            }
            #pragma unroll
            for (int j = 0; j < GTN; j += 4) {
                float4 v = *(const float4*)(&Bs[k][tCol + j]);
                regN[j] = v.x; regN[j+1] = v.y; regN[j+2] = v.z; regN[j+3] = v.w;
            }
            #pragma unroll
            for (int i = 0; i < GTM; ++i)
                #pragma unroll
                for (int j = 0; j < GTN; ++j)
                    acc[i][j] = fmaf(regM[i], regN[j], acc[i][j]);
        }
        __syncthreads();
    }

    #pragma unroll
    for (int i = 0; i < GTM; ++i)
        #pragma unroll
        for (int j = 0; j < GTN; j += 4) {
            float4 v = make_float4(acc[i][j], acc[i][j+1], acc[i][j+2], acc[i][j+3]);
            *(float4*)(C + (long)(tRow + i) * N + tCol + j) = v;
        }
}

// ---------------------------------------------------------------------------
// Flash attention with position-prefix causal mask.
// Block = 128 threads = 128 query rows for one (b,h). K/V tiles of 64 rows in
// SMEM; each thread keeps q[64], o[64] in registers and processes keys in
// 16-wide register chunks with online softmax.
// Mask: attend iff pos_k <= pos_q. Positions sorted -> contiguous prefix,
// monotone in i -> block-level early exit when tile's first key pos exceeds
// the block's last query pos.
// ---------------------------------------------------------------------------
#define QT 128
#define KT 64
#define KC 16

__global__ __launch_bounds__(128)
void attn_kernel(const float* __restrict__ qkv, const int* __restrict__ pos,
                 float* __restrict__ out)
{
    __shared__ float Ks[KT][HDim];
    __shared__ float Vs[KT][HDim];
    __shared__ int   pk[KT];

    const int t  = threadIdx.x;
    const int qt = blockIdx.x;   // query tile
    const int h  = blockIdx.y;
    const int b  = blockIdx.z;

    const int qi = qt * QT + t;
    const long rowQ = (long)(b * Tv + qi) * QKVN + h * HDim;

    float q[HDim];
    #pragma unroll
    for (int d = 0; d < HDim; d += 4) {
        float4 v = *(const float4*)(qkv + rowQ + d);
        q[d] = v.x; q[d+1] = v.y; q[d+2] = v.z; q[d+3] = v.w;
    }
    const int pq     = pos[b * Tv + qi];
    const int p_last = pos[b * Tv + qt * QT + QT - 1];

    float o[HDim];
    #pragma unroll
    for (int d = 0; d < HDim; ++d) o[d] = 0.f;
    float m = -1e30f, l = 0.f;
    const float scale = 0.125f;  // 1/sqrt(64)

    for (int k0 = 0; k0 < Tv; k0 += KT) {
        __syncthreads();
        if (t < KT) pk[t] = pos[b * Tv + k0 + t];
        {
            const int r  = t >> 1;
            const int c0 = (t & 1) * 32;
            const long rowK = (long)(b * Tv + k0 + r) * QKVN + Dv + h * HDim + c0;
            const long rowV = rowK + Dv;
            #pragma unroll
            for (int cc = 0; cc < 32; cc += 4) {
                *(float4*)(&Ks[r][c0 + cc]) = *(const float4*)(qkv + rowK + cc);
                *(float4*)(&Vs[r][c0 + cc]) = *(const float4*)(qkv + rowV + cc);
            }
        }
        __syncthreads();
        if (pk[0] > p_last) break;   // uniform across block

        #pragma unroll 1
        for (int j0 = 0; j0 < KT; j0 += KC) {
            float s[KC];
            float tmax = -1e30f;
            #pragma unroll
            for (int j = 0; j < KC; ++j) {
                float a0 = 0.f, a1 = 0.f, a2 = 0.f, a3 = 0.f;
                const float4* kr = (const float4*)(&Ks[j0 + j][0]);
                #pragma unroll
                for (int d4 = 0; d4 < HDim / 4; ++d4) {
                    float4 kv = kr[d4];
                    a0 = fmaf(q[d4*4+0], kv.x, a0);
                    a1 = fmaf(q[d4*4+1], kv.y, a1);
                    a2 = fmaf(q[d4*4+2], kv.z, a2);
                    a3 = fmaf(q[d4*4+3], kv.w, a3);
                }
                float sc = ((a0 + a1) + (a2 + a3)) * scale;
                if (pk[j0 + j] > pq) sc = -1e30f;
                s[j] = sc;
                tmax = fmaxf(tmax, sc);
            }
            if (tmax > -1e29f) {     // at least one unmasked key in this chunk
                const float mn   = fmaxf(m, tmax);
                const float corr = __expf(m - mn);
                m = mn;
                float ls = 0.f;
                #pragma unroll
                for (int j = 0; j < KC; ++j) {
                    float p = __expf(s[j] - mn);
                    s[j] = p;
                    ls += p;
                }
                l = l * corr + ls;
                #pragma unroll
                for (int d = 0; d < HDim; ++d) o[d] *= corr;
                #pragma unroll
                for (int j = 0; j < KC; ++j) {
                    const float p = s[j];
                    const float4* vr = (const float4*)(&Vs[j0 + j][0]);
                    #pragma unroll
                    for (int d4 = 0; d4 < HDim / 4; ++d4) {
                        float4 vv = vr[d4];
                        o[d4*4+0] = fmaf(p, vv.x, o[d4*4+0]);
                        o[d4*4+1] = fmaf(p, vv.y, o[d4*4+1]);
                        o[d4*4+2] = fmaf(p, vv.z, o[d4*4+2]);
                        o[d4*4+3] = fmaf(p, vv.w, o[d4*4+3]);
                    }
                }
            }
        }
    }

    const float inv_l = 1.f / l;   // l > 0: self is always unmasked
    float* orow = out + (long)(b * Tv + qi) * Dv + h * HDim;
    #pragma unroll
    for (int d = 0; d < HDim; d += 4) {
        float4 v = make_float4(o[d] * inv_l, o[d+1] * inv_l,
                               o[d+2] * inv_l, o[d+3] * inv_l);
        *(float4*)(orow + d) = v;
    }
}

// ---------------------------------------------------------------------------
// Launch
// ---------------------------------------------------------------------------
extern "C" void kernel_launch(void* const* d_in, const int* in_sizes, int n_in,
                              void* d_out, int out_size)
{
    const float* x    = (const float*)d_in[0];
    const int*   pos  = (const int*)d_in[1];
    const float* Wqkv = (const float*)d_in[2];
    const float* Wout = (const float*)d_in[3];
    float*       outp = (float*)d_out;

    float* qkv_ptr = nullptr;
    float* attn_ptr = nullptr;
    cudaGetSymbolAddress((void**)&qkv_ptr,  g_qkv);
    cudaGetSymbolAddress((void**)&attn_ptr, g_attn);

    // 1) QKV projection: (8192,1024) @ (1024,3072)
    {
        dim3 grid(QKVN / GBN, BT / GBM);
        sgemm128<<<grid, 256>>>(x, Wqkv, qkv_ptr, BT, QKVN, Dv);
    }
    // 2) Attention
    {
        dim3 grid(Tv / QT, NH, Bv);
        attn_kernel<<<grid, 128>>>(qkv_ptr, pos, attn_ptr);
    }
    // 3) Output projection: (8192,1024) @ (1024,1024)
    {
        dim3 grid(Dv / GBN, BT / GBM);
        sgemm128<<<grid, 256>>>(attn_ptr, Wout, outp, BT, Dv, Dv);
    }
}

// round 3
// speedup vs baseline: 1.3154x; 1.3154x over previous
#include <cuda_runtime.h>
#include <cuda_bf16.h>
#include <cstdint>

// Problem constants
#define Bv   4
#define Tv   2048
#define Dv   1024
#define NH   16
#define HDim 64
#define BT   (Bv * Tv)          // 8192
#define QKVN (3 * Dv)           // 3072
#define KEFF (3 * Dv)           // 3072 (split-K: A=[hi|hi|lo], B=[hi|lo|hi])

// ---------------------------------------------------------------------------
// Scratch (device globals; no allocation allowed)
// ---------------------------------------------------------------------------
__device__ float         g_qkv[BT * QKVN];            // fp32 qkv           96MB
__device__ float         g_attn[BT * Dv];             // fp32 attn out      32MB
__device__ __nv_bfloat16 g_A1[(size_t)BT * KEFF];     // x split            48MB
__device__ __nv_bfloat16 g_A2[(size_t)BT * KEFF];     // attn-out split     48MB
__device__ __nv_bfloat16 g_Bt1[(size_t)QKVN * KEFF];  // Wqkv^T split       18MB
__device__ __nv_bfloat16 g_Bt2[(size_t)Dv * KEFF];    // Wout^T split        6MB

// ---------------------------------------------------------------------------
// Helpers (all base-target instructions: cp.async, ldmatrix, mma.sync)
// ---------------------------------------------------------------------------
__device__ __forceinline__ uint32_t smem_u32(const void* p) {
    uint32_t a;
    asm("{ .reg .u64 t; cvta.to.shared.u64 t, %1; cvt.u32.u64 %0, t; }" : "=r"(a) : "l"(p));
    return a;
}
__device__ __forceinline__ void cp_async16(uint32_t dst, const void* src) {
    asm volatile("cp.async.cg.shared.global [%0], [%1], 16;" :: "r"(dst), "l"(src));
}
__device__ __forceinline__ void cp_commit() {
    asm volatile("cp.async.commit_group;" ::: "memory");
}
template <int N>
__device__ __forceinline__ void cp_wait() {
    asm volatile("cp.async.wait_group %0;" :: "n"(N) : "memory");
}
__device__ __forceinline__ void ldm_x4(uint32_t* r, uint32_t addr) {
    asm volatile("ldmatrix.sync.aligned.m8n8.x4.shared.b16 {%0,%1,%2,%3}, [%4];"
                 : "=r"(r[0]), "=r"(r[1]), "=r"(r[2]), "=r"(r[3]) : "r"(addr));
}
__device__ __forceinline__ void ldm_x2(uint32_t* r, uint32_t addr) {
    asm volatile("ldmatrix.sync.aligned.m8n8.x2.shared.b16 {%0,%1}, [%2];"
                 : "=r"(r[0]), "=r"(r[1]) : "r"(addr));
}
__device__ __forceinline__ void mma_bf16(float* d, const uint32_t* a, const uint32_t* b) {
    asm volatile(
        "mma.sync.aligned.m16n8k16.row.col.f32.bf16.bf16.f32 "
        "{%0,%1,%2,%3}, {%4,%5,%6,%7}, {%8,%9}, {%0,%1,%2,%3};"
        : "+f"(d[0]), "+f"(d[1]), "+f"(d[2]), "+f"(d[3])
        : "r"(a[0]), "r"(a[1]), "r"(a[2]), "r"(a[3]), "r"(b[0]), "r"(b[1]));
}

// ---------------------------------------------------------------------------
// bf16 HMMA GEMM: C[M,N] = A[M,KEFF] @ Bt[N,KEFF]^T (both K-contiguous)
// 128x128 CTA tile, BK=32, 8 warps (warp tile 64x32), 3-stage cp.async pipe.
// ---------------------------------------------------------------------------
#define BM 128
#define BN 128
#define BK 32
#define KPAD 40                 // 80B row pitch -> conflict-free ldmatrix
#define GSTAGES 3
#define KITERS (KEFF / BK)      // 96
#define STAGE_ELEMS ((BM + BN) * KPAD)
#define GEMM_SMEM (GSTAGES * STAGE_ELEMS * 2)   // 61440 bytes

__global__ void __launch_bounds__(256)
gemm_mma(const __nv_bfloat16* __restrict__ A, const __nv_bfloat16* __restrict__ Bt,
         float* __restrict__ C, int N)
{
    extern __shared__ __nv_bfloat16 sm[];
    const int tid  = threadIdx.x;
    const int lane = tid & 31;
    const int wid  = tid >> 5;
    const int wm   = (wid & 1) * 64;    // warp M offset in tile
    const int wn   = (wid >> 1) * 32;   // warp N offset in tile
    const int m0   = blockIdx.y * BM;
    const int n0   = blockIdx.x * BN;

    const uint32_t smb = smem_u32(sm);

    // per-thread cp.async source/dest precompute
    const int idxA0 = tid * 2;              // two A 16B-chunks per thread
    const int rowA0 = idxA0 >> 2, kcA0 = (idxA0 & 3) * 8;
    const int rowA1 = (idxA0 + 1) >> 2, kcA1 = ((idxA0 + 1) & 3) * 8;

    float acc[4][4][4] = {};

    #define ISSUE_STAGE(it, s) do { \
        const __nv_bfloat16* ga = A  + (size_t)m0 * KEFF + (it) * BK; \
        const __nv_bfloat16* gb = Bt + (size_t)n0 * KEFF + (it) * BK; \
        uint32_t sa = smb + (uint32_t)(s) * STAGE_ELEMS * 2; \
        uint32_t sb = sa + BM * KPAD * 2; \
        cp_async16(sa + (rowA0 * KPAD + kcA0) * 2, ga + (size_t)rowA0 * KEFF + kcA0); \
        cp_async16(sa + (rowA1 * KPAD + kcA1) * 2, ga + (size_t)rowA1 * KEFF + kcA1); \
        cp_async16(sb + (rowA0 * KPAD + kcA0) * 2, gb + (size_t)rowA0 * KEFF + kcA0); \
        cp_async16(sb + (rowA1 * KPAD + kcA1) * 2, gb + (size_t)rowA1 * KEFF + kcA1); \
    } while (0)

    #pragma unroll
    for (int s = 0; s < GSTAGES; ++s) { ISSUE_STAGE(s, s); cp_commit(); }

    // ldmatrix address components (stage-invariant parts)
    const int aRowSel = wm + (lane & 15);          // + mt*16
    const int aColSel = (lane >> 4) << 3;          // + k0
    const int bRowSel = wn + (lane & 7);           // + nt*8
    const int bColSel = ((lane >> 3) & 1) << 3;    // + k0

    for (int it = 0; it < KITERS; ++it) {
        const int s = it % GSTAGES;
        cp_wait<GSTAGES - 1>();
        __syncthreads();

        const uint32_t sa = smb + (uint32_t)s * STAGE_ELEMS * 2;
        const uint32_t sb = sa + BM * KPAD * 2;

        #pragma unroll
        for (int ks = 0; ks < 2; ++ks) {
            const int k0 = ks * 16;
            uint32_t afr[4][4], bfr[4][2];
            #pragma unroll
            for (int mt = 0; mt < 4; ++mt)
                ldm_x4(afr[mt], sa + ((aRowSel + mt * 16) * KPAD + k0 + aColSel) * 2);
            #pragma unroll
            for (int nt = 0; nt < 4; ++nt)
                ldm_x2(bfr[nt], sb + ((bRowSel + nt * 8) * KPAD + k0 + bColSel) * 2);
            #pragma unroll
            for (int mt = 0; mt < 4; ++mt)
                #pragma unroll
                for (int nt = 0; nt < 4; ++nt)
                    mma_bf16(acc[mt][nt], afr[mt], bfr[nt]);
        }
        __syncthreads();
        if (it + GSTAGES < KITERS) { ISSUE_STAGE(it + GSTAGES, s); cp_commit(); }
    }

    // Epilogue: direct fp32 stores (8B per element pair)
    const int er = lane >> 2;
    const int ec = (lane & 3) * 2;
    #pragma unroll
    for (int mt = 0; mt < 4; ++mt) {
        #pragma unroll
        for (int nt = 0; nt < 4; ++nt) {
            const int r  = m0 + wm + mt * 16 + er;
            const int cc = n0 + wn + nt * 8 + ec;
            *(float2*)(C + (size_t)r * N + cc)       = make_float2(acc[mt][nt][0], acc[mt][nt][1]);
            *(float2*)(C + (size_t)(r + 8) * N + cc) = make_float2(acc[mt][nt][2], acc[mt][nt][3]);
        }
    }
    #undef ISSUE_STAGE
}

// ---------------------------------------------------------------------------
// fp32 -> bf16 hi/lo split conversions
// A layout: [hi | hi | lo] along K; B layout (transposed): [hi | lo | hi]
// ---------------------------------------------------------------------------
__global__ void conv_split_A(const float* __restrict__ src, __nv_bfloat16* __restrict__ dst, int K)
{
    long t = (long)blockIdx.x * blockDim.x + threadIdx.x;
    long total = (long)BT * K;
    if (t >= total) return;
    long m = t / K, k = t - m * K;
    float a = src[t];
    __nv_bfloat16 hi = __float2bfloat16(a);
    __nv_bfloat16 lo = __float2bfloat16(a - __bfloat162float(hi));
    long base = m * (3L * K) + k;
    dst[base]         = hi;
    dst[base + K]     = hi;
    dst[base + 2 * K] = lo;
}

// W[K][N] row-major -> Bt[n][3K] = [hi | lo | hi], SMEM-tiled transpose
__global__ void conv_split_W(const float* __restrict__ W, __nv_bfloat16* __restrict__ Bt,
                             int K, int N)
{
    __shared__ float tile[32][33];
    const int k0 = blockIdx.y * 32, n0 = blockIdx.x * 32;
    for (int i = threadIdx.y; i < 32; i += 8)
        tile[i][threadIdx.x] = W[(long)(k0 + i) * N + n0 + threadIdx.x];
    __syncthreads();
    for (int i = threadIdx.y; i < 32; i += 8) {
        int n = n0 + i, k = k0 + threadIdx.x;
        float a = tile[threadIdx.x][i];
        __nv_bfloat16 hi = __float2bfloat16(a);
        __nv_bfloat16 lo = __float2bfloat16(a - __bfloat162float(hi));
        long base = (long)n * (3L * K) + k;
        Bt[base]         = hi;
        Bt[base + K]     = lo;
        Bt[base + 2 * K] = hi;
    }
}

// ---------------------------------------------------------------------------
// Flash attention (fp32 SIMT; unchanged — next round's target)
// ---------------------------------------------------------------------------
#define QT 128
#define KT 64
#define KC 16

__global__ __launch_bounds__(128)
void attn_kernel(const float* __restrict__ qkv, const int* __restrict__ pos,
                 float* __restrict__ out)
{
    __shared__ float Ks[KT][HDim];
    __shared__ float Vs[KT][HDim];
    __shared__ int   pk[KT];

    const int t  = threadIdx.x;
    const int qt = blockIdx.x;
    const int h  = blockIdx.y;
    const int b  = blockIdx.z;

    const int qi = qt * QT + t;
    const long rowQ = (long)(b * Tv + qi) * QKVN + h * HDim;

    float q[HDim];
    #pragma unroll
    for (int d = 0; d < HDim; d += 4) {
        float4 v = *(const float4*)(qkv + rowQ + d);
        q[d] = v.x; q[d+1] = v.y; q[d+2] = v.z; q[d+3] = v.w;
    }
    const int pq     = pos[b * Tv + qi];
    const int p_last = pos[b * Tv + qt * QT + QT - 1];

    float o[HDim];
    #pragma unroll
    for (int d = 0; d < HDim; ++d) o[d] = 0.f;
    float m = -1e30f, l = 0.f;
    const float scale = 0.125f;

    for (int k0 = 0; k0 < Tv; k0 += KT) {
        __syncthreads();
        if (t < KT) pk[t] = pos[b * Tv + k0 + t];
        {
            const int r  = t >> 1;
            const int c0 = (t & 1) * 32;
            const long rowK = (long)(b * Tv + k0 + r) * QKVN + Dv + h * HDim + c0;
            const long rowV = rowK + Dv;
            #pragma unroll
            for (int cc = 0; cc < 32; cc += 4) {
                *(float4*)(&Ks[r][c0 + cc]) = *(const float4*)(qkv + rowK + cc);
                *(float4*)(&Vs[r][c0 + cc]) = *(const float4*)(qkv + rowV + cc);
            }
        }
        __syncthreads();
        if (pk[0] > p_last) break;

        #pragma unroll 1
        for (int j0 = 0; j0 < KT; j0 += KC) {
            float s[KC];
            float tmax = -1e30f;
            #pragma unroll
            for (int j = 0; j < KC; ++j) {
                float a0 = 0.f, a1 = 0.f, a2 = 0.f, a3 = 0.f;
                const float4* kr = (const float4*)(&Ks[j0 + j][0]);
                #pragma unroll
                for (int d4 = 0; d4 < HDim / 4; ++d4) {
                    float4 kv = kr[d4];
                    a0 = fmaf(q[d4*4+0], kv.x, a0);
                    a1 = fmaf(q[d4*4+1], kv.y, a1);
                    a2 = fmaf(q[d4*4+2], kv.z, a2);
                    a3 = fmaf(q[d4*4+3], kv.w, a3);
                }
                float sc = ((a0 + a1) + (a2 + a3)) * scale;
                if (pk[j0 + j] > pq) sc = -1e30f;
                s[j] = sc;
                tmax = fmaxf(tmax, sc);
            }
            if (tmax > -1e29f) {
                const float mn   = fmaxf(m, tmax);
                const float corr = __expf(m - mn);
                m = mn;
                float ls = 0.f;
                #pragma unroll
                for (int j = 0; j < KC; ++j) {
                    float p = __expf(s[j] - mn);
                    s[j] = p;
                    ls += p;
                }
                l = l * corr + ls;
                #pragma unroll
                for (int d = 0; d < HDim; ++d) o[d] *= corr;
                #pragma unroll
                for (int j = 0; j < KC; ++j) {
                    const float p = s[j];
                    const float4* vr = (const float4*)(&Vs[j0 + j][0]);
                    #pragma unroll
                    for (int d4 = 0; d4 < HDim / 4; ++d4) {
                        float4 vv = vr[d4];
                        o[d4*4+0] = fmaf(p, vv.x, o[d4*4+0]);
                        o[d4*4+1] = fmaf(p, vv.y, o[d4*4+1]);
                        o[d4*4+2] = fmaf(p, vv.z, o[d4*4+2]);
                        o[d4*4+3] = fmaf(p, vv.w, o[d4*4+3]);
                    }
                }
            }
        }
    }

    const float inv_l = 1.f / l;
    float* orow = out + (long)(b * Tv + qi) * Dv + h * HDim;
    #pragma unroll
    for (int d = 0; d < HDim; d += 4) {
        float4 v = make_float4(o[d] * inv_l, o[d+1] * inv_l,
                               o[d+2] * inv_l, o[d+3] * inv_l);
        *(float4*)(orow + d) = v;
    }
}

// ---------------------------------------------------------------------------
// Launch
// ---------------------------------------------------------------------------
extern "C" void kernel_launch(void* const* d_in, const int* in_sizes, int n_in,
                              void* d_out, int out_size)
{
    const float* x    = (const float*)d_in[0];
    const int*   pos  = (const int*)d_in[1];
    const float* Wqkv = (const float*)d_in[2];
    const float* Wout = (const float*)d_in[3];
    float*       outp = (float*)d_out;

    float *qkv_p, *attn_p;
    __nv_bfloat16 *A1_p, *A2_p, *Bt1_p, *Bt2_p;
    cudaGetSymbolAddress((void**)&qkv_p,  g_qkv);
    cudaGetSymbolAddress((void**)&attn_p, g_attn);
    cudaGetSymbolAddress((void**)&A1_p,   g_A1);
    cudaGetSymbolAddress((void**)&A2_p,   g_A2);
    cudaGetSymbolAddress((void**)&Bt1_p,  g_Bt1);
    cudaGetSymbolAddress((void**)&Bt2_p,  g_Bt2);

    cudaFuncSetAttribute(gemm_mma, cudaFuncAttributeMaxDynamicSharedMemorySize, GEMM_SMEM);

    // 1) Split-convert x & Wqkv
    {
        long total = (long)BT * Dv;
        conv_split_A<<<(unsigned)((total + 255) / 256), 256>>>(x, A1_p, Dv);
        dim3 gw(QKVN / 32, Dv / 32);
        conv_split_W<<<gw, dim3(32, 8)>>>(Wqkv, Bt1_p, Dv, QKVN);
    }
    // 2) QKV projection (HMMA)
    {
        dim3 grid(QKVN / BN, BT / BM);
        gemm_mma<<<grid, 256, GEMM_SMEM>>>(A1_p, Bt1_p, qkv_p, QKVN);
    }
    // 3) Attention
    {
        dim3 grid(Tv / QT, NH, Bv);
        attn_kernel<<<grid, 128>>>(qkv_p, pos, attn_p);
    }
    // 4) Split-convert attn output & Wout, then output projection (HMMA)
    {
        long total = (long)BT * Dv;
        conv_split_A<<<(unsigned)((total + 255) / 256), 256>>>(attn_p, A2_p, Dv);
        dim3 gw(Dv / 32, Dv / 32);
        conv_split_W<<<gw, dim3(32, 8)>>>(Wout, Bt2_p, Dv, Dv);
        dim3 grid(Dv / BN, BT / BM);
        gemm_mma<<<grid, 256, GEMM_SMEM>>>(A2_p, Bt2_p, outp, Dv);
    }
}